// round 4
// baseline (speedup 1.0000x reference)
#include <cuda_runtime.h>
#include <cstdint>

#define BS 256
#define D  2048
#define H  1024
#define C  200
#define NC 112

// ---------------- scratch (static device allocations only) ----------------
__device__ float g_y1[C * H];        // 1 + l2norm(y_embedding)
__device__ float g_c1[2 * NC * H];   // 1 + l2norm(c_embedding)
__device__ float g_hxy[BS * H];      // dropout(x @ xy_fc1^T + b)
__device__ float g_hxc[BS * H];      // dropout(x @ xc_fc1^T + b)
__device__ float g_pn[NC * H];       // sum_h ce_neg[n,h] * W[j, n*H+h]
__device__ float g_pd[NC * H];       // sum_h (ce_pos-ce_neg)[n,h] * W[j, n*H+h]
__device__ float g_cproj[BS * H];

// ---------------- packed f32x2 helpers -------------------------------------
__device__ __forceinline__ uint64_t pack2(float x, float y) {
    uint64_t r;
    asm("mov.b64 %0, {%1, %2};" : "=l"(r) : "f"(x), "f"(y));
    return r;
}
__device__ __forceinline__ void fma2(uint64_t& d, uint64_t a, uint64_t b) {
    asm("fma.rn.f32x2 %0, %1, %2, %0;" : "+l"(d) : "l"(a), "l"(b));
}
__device__ __forceinline__ float2 unpack2(uint64_t v) {
    float2 f;
    asm("mov.b64 {%0, %1}, %2;" : "=f"(f.x), "=f"(f.y) : "l"(v));
    return f;
}

// ---------------- JAX threefry2x32 (partitionable semantics) --------------
__device__ __forceinline__ uint32_t rotl32(uint32_t v, int r) {
    return (v << r) | (v >> (32 - r));
}

__device__ __forceinline__ void tf2x32(uint32_t k0, uint32_t k1,
                                       uint32_t x0, uint32_t x1,
                                       uint32_t& o0, uint32_t& o1) {
    uint32_t ks2 = k0 ^ k1 ^ 0x1BD11BDAu;
    x0 += k0; x1 += k1;
#define TF_R(r) { x0 += x1; x1 = rotl32(x1, r); x1 ^= x0; }
    TF_R(13) TF_R(15) TF_R(26) TF_R(6)   x0 += k1;  x1 += ks2 + 1u;
    TF_R(17) TF_R(29) TF_R(16) TF_R(24)  x0 += ks2; x1 += k0 + 2u;
    TF_R(13) TF_R(15) TF_R(26) TF_R(6)   x0 += k0;  x1 += k1 + 3u;
    TF_R(17) TF_R(29) TF_R(16) TF_R(24)  x0 += k1;  x1 += ks2 + 4u;
    TF_R(13) TF_R(15) TF_R(26) TF_R(6)   x0 += ks2; x1 += k0 + 5u;
#undef TF_R
    o0 = x0; o1 = x1;
}

__device__ __forceinline__ bool drop_keep(uint32_t ka, uint32_t kb, uint32_t idx) {
    uint32_t a, b;
    tf2x32(ka, kb, 0u, idx, a, b);
    uint32_t bits = a ^ b;
    float u = __uint_as_float((bits >> 9) | 0x3F800000u) - 1.0f;
    return u < 0.8f;
}

// ---------------- shared-memory overlays ----------------------------------
struct SmemFc1  { float As[32][34]; float Bs[32][64]; };                  // 12544 B
struct SmemNorm { float red[256]; };
struct SmemCp   { float As[16][64]; float Bs[16][64]; float base[64]; };
struct SmemXY   { float Hs[32][33]; float Ys[32][33]; float ws[32]; };
struct SmemXC   { float Hs[32][33]; float Cs[32][17]; float Ws[32][9]; };

#define SMEM_BYTES 16384

// ---------------- part: 1 + l2norm of one row ------------------------------
__device__ void part_norm(char* smem, int r,
                          const float* __restrict__ ye,
                          const float* __restrict__ ce) {
    SmemNorm& s = *reinterpret_cast<SmemNorm*>(smem);
    const float* src;
    float* dst;
    if (r < C) { src = ye + (size_t)r * H;        dst = g_y1 + (size_t)r * H; }
    else       { src = ce + (size_t)(r - C) * H;  dst = g_c1 + (size_t)(r - C) * H; }
    int t = threadIdx.x;
    float4 v = *reinterpret_cast<const float4*>(&src[t * 4]);
    s.red[t] = v.x * v.x + v.y * v.y + v.z * v.z + v.w * v.w;
    __syncthreads();
    for (int o = 128; o; o >>= 1) {
        if (t < o) s.red[t] += s.red[t + o];
        __syncthreads();
    }
    float n = fmaxf(sqrtf(s.red[0]), 1e-12f);
    dst[t * 4 + 0] = 1.0f + v.x / n;
    dst[t * 4 + 1] = 1.0f + v.y / n;
    dst[t * 4 + 2] = 1.0f + v.z / n;
    dst[t * 4 + 3] = 1.0f + v.w / n;
}

// ---------------- part: fc1 GEMM (f32x2) + bias + dropout ------------------
// tile: m=32 (batch), n=64 (H cols), k-chunk 32
__device__ void part_fc1(char* smem, int which, int n0, int m0,
                         const float* __restrict__ x,
                         const float* __restrict__ W,
                         const float* __restrict__ B,
                         float* __restrict__ out) {
    SmemFc1& s = *reinterpret_cast<SmemFc1*>(smem);
    const int tid = threadIdx.x;
    const int tx = tid % 16, ty = tid / 16;   // tx: 4-col groups, ty: 2-row groups
    const int lr = tid / 8;          // 0..31
    const int lc = (tid % 8) * 4;    // 0..28
    uint64_t acc[2][2] = {};         // 2 m-rows x 2 f32x2 pairs (4 n-cols)
    for (int k0 = 0; k0 < D; k0 += 32) {
        {
            float4 va = *reinterpret_cast<const float4*>(&x[(size_t)(m0 + lr) * D + k0 + lc]);
            s.As[lc + 0][lr] = va.x; s.As[lc + 1][lr] = va.y;
            s.As[lc + 2][lr] = va.z; s.As[lc + 3][lr] = va.w;
#pragma unroll
            for (int rr = 0; rr < 2; rr++) {
                int r = lr + rr * 32;
                float4 vb = *reinterpret_cast<const float4*>(&W[(size_t)(n0 + r) * D + k0 + lc]);
                s.Bs[lc + 0][r] = vb.x; s.Bs[lc + 1][r] = vb.y;
                s.Bs[lc + 2][r] = vb.z; s.Bs[lc + 3][r] = vb.w;
            }
        }
        __syncthreads();
#pragma unroll
        for (int kk = 0; kk < 32; kk++) {
            float a0 = s.As[kk][ty * 2 + 0];
            float a1 = s.As[kk][ty * 2 + 1];
            uint64_t ap0 = pack2(a0, a0);
            uint64_t ap1 = pack2(a1, a1);
            const uint64_t* bp = reinterpret_cast<const uint64_t*>(&s.Bs[kk][tx * 4]);
            uint64_t b0 = bp[0], b1 = bp[1];
            fma2(acc[0][0], ap0, b0); fma2(acc[0][1], ap0, b1);
            fma2(acc[1][0], ap1, b0); fma2(acc[1][1], ap1, b1);
        }
        __syncthreads();
    }
    uint32_t ka, kb;
    tf2x32(0u, 42u, 0u, (uint32_t)which, ka, kb);
#pragma unroll
    for (int i = 0; i < 2; i++) {
        int b = m0 + ty * 2 + i;
#pragma unroll
        for (int jp = 0; jp < 2; jp++) {
            float2 v = unpack2(acc[i][jp]);
            int col = n0 + tx * 4 + jp * 2;
            float h0 = v.x + B[col];
            float h1 = v.y + B[col + 1];
            uint32_t i0 = (uint32_t)(b * H + col);
            out[(size_t)b * H + col]     = drop_keep(ka, kb, i0)      ? h0 / 0.8f : 0.0f;
            out[(size_t)b * H + col + 1] = drop_keep(ka, kb, i0 + 1u) ? h1 / 0.8f : 0.0f;
        }
    }
}

// ---------------- part: stream concept_proj_w once (no smem) ----------------
// warp handles 4 consecutive j rows of concept n; ep/en via L1-cached LDG
__device__ void part_pnd(int n, int jg,
                         const float* __restrict__ ce,
                         const float* __restrict__ W) {
    const int tid = threadIdx.x;
    const int w = tid >> 5, lane = tid & 31;
    const int j0 = (jg * 8 + w) * 4;
    const float* ep = ce + (size_t)n * H;
    const float* en = ce + (size_t)(NC + n) * H;
    const size_t rs = (size_t)NC * H;
    const float* Wr = W + (size_t)j0 * rs + (size_t)n * H;
    float an[4] = {}, ap[4] = {};
#pragma unroll
    for (int c = 0; c < 8; c++) {
        int hh = c * 128 + lane * 4;
        float4 e_p = *reinterpret_cast<const float4*>(&ep[hh]);
        float4 e_n = *reinterpret_cast<const float4*>(&en[hh]);
#pragma unroll
        for (int r = 0; r < 4; r++) {
            float4 wv = *reinterpret_cast<const float4*>(&Wr[(size_t)r * rs + hh]);
            ap[r] += wv.x * e_p.x + wv.y * e_p.y + wv.z * e_p.z + wv.w * e_p.w;
            an[r] += wv.x * e_n.x + wv.y * e_n.y + wv.z * e_n.z + wv.w * e_n.w;
        }
    }
#pragma unroll
    for (int off = 16; off; off >>= 1) {
#pragma unroll
        for (int r = 0; r < 4; r++) {
            ap[r] += __shfl_down_sync(0xFFFFFFFFu, ap[r], off);
            an[r] += __shfl_down_sync(0xFFFFFFFFu, an[r], off);
        }
    }
    if (lane == 0) {
#pragma unroll
        for (int r = 0; r < 4; r++) {
            g_pn[n * H + j0 + r] = an[r];
            g_pd[n * H + j0 + r] = ap[r] - an[r];
        }
    }
}

// ---------------- part: c_proj = (bias + sum_n pn) + gt @ pd ----------------
__device__ void part_cproj(char* smem, int j0, int m0,
                           const int* __restrict__ cgt,
                           const float* __restrict__ bias) {
    SmemCp& s = *reinterpret_cast<SmemCp*>(smem);
    const int tid = threadIdx.x;
    {
        int col = j0 + (tid & 63);
        if (tid < 64) s.base[tid] = bias[col];
        __syncthreads();
        int nb = (tid >> 6) * 28;
        float part = 0.f;
#pragma unroll 4
        for (int n = nb; n < nb + 28; n++) part += g_pn[n * H + col];
        atomicAdd(&s.base[tid & 63], part);
    }
    const int tx = tid % 16, ty = tid / 16;
    float acc[4][4] = {};
    for (int k0 = 0; k0 < NC; k0 += 16) {
        __syncthreads();
        {
            int r = tid / 4;
            int c = (tid % 4) * 4;
            int b = m0 + r;
#pragma unroll
            for (int q = 0; q < 4; q++)
                s.As[c + q][r] = (cgt[(size_t)b * NC + k0 + c + q] == 1) ? 1.0f : 0.0f;
        }
        {
            int kk = tid / 16;
            int j4 = (tid % 16) * 4;
            float4 v = *reinterpret_cast<const float4*>(&g_pd[(size_t)(k0 + kk) * H + j0 + j4]);
            *reinterpret_cast<float4*>(&s.Bs[kk][j4]) = v;
        }
        __syncthreads();
#pragma unroll
        for (int kk = 0; kk < 16; kk++) {
            float4 a = *reinterpret_cast<const float4*>(&s.As[kk][ty * 4]);
            float4 b = *reinterpret_cast<const float4*>(&s.Bs[kk][tx * 4]);
            float av[4] = {a.x, a.y, a.z, a.w};
            float bv[4] = {b.x, b.y, b.z, b.w};
#pragma unroll
            for (int i = 0; i < 4; i++)
#pragma unroll
                for (int j = 0; j < 4; j++)
                    acc[i][j] = fmaf(av[i], bv[j], acc[i][j]);
        }
    }
#pragma unroll
    for (int i = 0; i < 4; i++) {
        int b = m0 + ty * 4 + i;
#pragma unroll
        for (int j = 0; j < 4; j++) {
            int col = j0 + tx * 4 + j;
            g_cproj[(size_t)b * H + col] = acc[i][j] + s.base[tx * 4 + j];
        }
    }
}

// ---------------- part: xy / cy energy --------------------------------------
__device__ void part_xycy(char* smem, int c0, int b0,
                          const float* __restrict__ A,
                          const float* __restrict__ clsw,
                          float bias,
                          float* __restrict__ out) {
    SmemXY& s = *reinterpret_cast<SmemXY*>(smem);
    const int tid = threadIdx.x;
    const int tx = tid % 16, ty = tid / 16;
    const int lr = tid / 8;
    const int lc = (tid % 8) * 4;
    float acc[2][2] = {};
    for (int k0 = 0; k0 < H; k0 += 32) {
        {
            float4 v = *reinterpret_cast<const float4*>(&A[(size_t)(b0 + lr) * H + k0 + lc]);
            s.Hs[lc + 0][lr] = v.x; s.Hs[lc + 1][lr] = v.y;
            s.Hs[lc + 2][lr] = v.z; s.Hs[lc + 3][lr] = v.w;
            int cr = c0 + lr; if (cr > C - 1) cr = C - 1;
            float4 u = *reinterpret_cast<const float4*>(&g_y1[(size_t)cr * H + k0 + lc]);
            s.Ys[lc + 0][lr] = u.x; s.Ys[lc + 1][lr] = u.y;
            s.Ys[lc + 2][lr] = u.z; s.Ys[lc + 3][lr] = u.w;
            if (tid < 32) s.ws[tid] = clsw[k0 + tid];
        }
        __syncthreads();
#pragma unroll
        for (int kk = 0; kk < 32; kk++) {
            float a0 = s.Hs[kk][ty * 2 + 0];
            float a1 = s.Hs[kk][ty * 2 + 1];
            float y0 = s.Ys[kk][tx * 2 + 0];
            float y1v = s.Ys[kk][tx * 2 + 1];
            float w = s.ws[kk];
            acc[0][0] = fmaf(fmaxf(a0 * y0, 0.f), w, acc[0][0]);
            acc[0][1] = fmaf(fmaxf(a0 * y1v, 0.f), w, acc[0][1]);
            acc[1][0] = fmaf(fmaxf(a1 * y0, 0.f), w, acc[1][0]);
            acc[1][1] = fmaf(fmaxf(a1 * y1v, 0.f), w, acc[1][1]);
        }
        __syncthreads();
    }
#pragma unroll
    for (int i = 0; i < 2; i++) {
        int b = b0 + ty * 2 + i;
#pragma unroll
        for (int j = 0; j < 2; j++) {
            int c = c0 + tx * 2 + j;
            if (c < C) out[(size_t)b * C + c] = acc[i][j] + bias;
        }
    }
}

// ---------------- part: xc energy -------------------------------------------
__device__ void part_xc(char* smem, int n0, int b0,
                        const float* __restrict__ xcw,
                        const float* __restrict__ xcb,
                        float* __restrict__ out) {
    SmemXC& s = *reinterpret_cast<SmemXC*>(smem);
    const int tid = threadIdx.x;
    const int tx = tid % 8;
    const int ty = tid / 8;
    const int lr = tid / 8;
    const int lc = (tid % 8) * 4;
    float acc0 = 0.f, acc1 = 0.f;
    for (int k0 = 0; k0 < H; k0 += 32) {
        {
            float4 v = *reinterpret_cast<const float4*>(&g_hxc[(size_t)(b0 + lr) * H + k0 + lc]);
            s.Hs[lc + 0][lr] = v.x; s.Hs[lc + 1][lr] = v.y;
            s.Hs[lc + 2][lr] = v.z; s.Hs[lc + 3][lr] = v.w;
        }
        {
            int loc = tid / 16;
            int kk = (tid % 16) * 2;
            int nl = loc >> 1, sx = loc & 1;
            int row = sx * NC + (n0 + nl);
            float2 v = *reinterpret_cast<const float2*>(&g_c1[(size_t)row * H + k0 + kk]);
            s.Cs[kk + 0][nl * 2 + sx] = v.x;
            s.Cs[kk + 1][nl * 2 + sx] = v.y;
        }
        {
            int nl = tid / 32;
            int kk = tid % 32;
            s.Ws[kk][nl] = xcw[(size_t)(n0 + nl) * H + k0 + kk];
        }
        __syncthreads();
#pragma unroll
        for (int kk = 0; kk < 32; kk++) {
            float h = s.Hs[kk][ty];
            float w = s.Ws[kk][tx];
            float cp = s.Cs[kk][tx * 2 + 0];
            float cn = s.Cs[kk][tx * 2 + 1];
            acc0 = fmaf(fmaxf(h * cp, 0.f), w, acc0);
            acc1 = fmaf(fmaxf(h * cn, 0.f), w, acc1);
        }
        __syncthreads();
    }
    int b = b0 + ty, n = n0 + tx;
    float bb = xcb[n];
    size_t base = (size_t)(2 * BS * C) + (size_t)b * (NC * 2) + n * 2;
    out[base + 0] = acc0 + bb;
    out[base + 1] = acc1 + bb;
}

// ================= launch 1: fc1 + norm + pnd (overlapped) ==================
#define L1_FC1   256                          // 2 x (8 m-tiles x 16 n-tiles)
#define L1_NORM  (C + 2 * NC)                 // 424
#define L1_PND   (NC * 32)                    // 3584 (32 j-groups of 32 j)
#define L1_GRID  (L1_FC1 + L1_NORM + L1_PND)

__global__ __launch_bounds__(256) void k_main(const float* __restrict__ x,
                                              const float* __restrict__ ye,
                                              const float* __restrict__ ce,
                                              const float* __restrict__ w0,
                                              const float* __restrict__ b0,
                                              const float* __restrict__ w1,
                                              const float* __restrict__ b1,
                                              const float* __restrict__ cpw) {
    __shared__ __align__(16) char smem[SMEM_BYTES];
    int bid = blockIdx.x;
    if (bid < L1_FC1) {
        int which = bid >> 7;
        int rem = bid & 127;
        part_fc1(smem, which, (rem % 16) * 64, (rem / 16) * 32, x,
                 which ? w1 : w0, which ? b1 : b0, which ? g_hxc : g_hxy);
    } else if (bid < L1_FC1 + L1_NORM) {
        part_norm(smem, bid - L1_FC1, ye, ce);
    } else {
        int p = bid - (L1_FC1 + L1_NORM);
        part_pnd(p % NC, p / NC, ce, cpw);
    }
}

// ================= launch 2: cproj + xy-energy + xc-energy ==================
#define L2_CP   (16 * 4)              // 64
#define L2_XY   (7 * 8)               // 56
#define L2_XC   (14 * 8)              // 112
#define L2_GRID (L2_CP + L2_XY + L2_XC)

__global__ __launch_bounds__(256) void k_mid(const int* __restrict__ cgt,
                                             const float* __restrict__ cpb,
                                             const float* __restrict__ clsxy_w,
                                             const float* __restrict__ clsxy_b,
                                             const float* __restrict__ xcw,
                                             const float* __restrict__ xcb,
                                             float* __restrict__ out) {
    __shared__ __align__(16) char smem[SMEM_BYTES];
    int bid = blockIdx.x;
    if (bid < L2_CP) {
        part_cproj(smem, (bid % 16) * 64, (bid / 16) * 64, cgt, cpb);
    } else if (bid < L2_CP + L2_XY) {
        int p = bid - L2_CP;
        part_xycy(smem, (p % 7) * 32, (p / 7) * 32, g_hxy, clsxy_w, clsxy_b[0], out);
    } else {
        int p = bid - (L2_CP + L2_XY);
        part_xc(smem, (p % 14) * 8, (p / 14) * 32, xcw, xcb, out);
    }
}

// ================= launch 3: cy-energy ======================================
__global__ __launch_bounds__(256) void k_cy(const float* __restrict__ clscy_w,
                                            const float* __restrict__ clscy_b,
                                            float* __restrict__ out) {
    __shared__ __align__(16) char smem[SMEM_BYTES];
    int bid = blockIdx.x;
    part_xycy(smem, (bid % 7) * 32, (bid / 7) * 32, g_cproj, clscy_w, clscy_b[0],
              out + (size_t)BS * C);
}

// ---------------- launch ----------------------------------------------------
extern "C" void kernel_launch(void* const* d_in, const int* in_sizes, int n_in,
                              void* d_out, int out_size) {
    (void)in_sizes; (void)n_in; (void)out_size;
    const float* x       = (const float*)d_in[0];
    const int*   c_gt    = (const int*)d_in[1];
    const float* y_emb   = (const float*)d_in[2];
    const float* c_emb   = (const float*)d_in[3];
    const float* xy_w    = (const float*)d_in[4];
    const float* xy_b    = (const float*)d_in[5];
    const float* xc_w1   = (const float*)d_in[6];
    const float* xc_b1   = (const float*)d_in[7];
    const float* clsxy_w = (const float*)d_in[8];
    const float* clsxy_b = (const float*)d_in[9];
    const float* clscy_w = (const float*)d_in[10];
    const float* clscy_b = (const float*)d_in[11];
    const float* xcw     = (const float*)d_in[12];
    const float* xcb     = (const float*)d_in[13];
    const float* cpw     = (const float*)d_in[14];
    const float* cpb     = (const float*)d_in[15];
    float* out = (float*)d_out;

    k_main<<<L1_GRID, 256>>>(x, y_emb, c_emb, xy_w, xy_b, xc_w1, xc_b1, cpw);
    k_mid<<<L2_GRID, 256>>>(c_gt, cpb, clsxy_w, clsxy_b, xcw, xcb, out);
    k_cy<<<7 * 8, 256>>>(clscy_w, clscy_b, out);
}

// round 5
// speedup vs baseline: 1.4653x; 1.4653x over previous
#include <cuda_runtime.h>
#include <cstdint>

#define BS 256
#define D  2048
#define H  1024
#define C  200
#define NC 112

// ---------------- scratch (static device allocations only) ----------------
__device__ float g_y1[C * H];
__device__ float g_c1[2 * NC * H];
__device__ float g_hxy[BS * H];
__device__ float g_hxc[BS * H];
__device__ float g_pn[NC * H];
__device__ float g_pd[NC * H];
__device__ float g_cproj[BS * H];

// ---------------- packed f32x2 helpers -------------------------------------
__device__ __forceinline__ uint64_t pack2(float x, float y) {
    uint64_t r;
    asm("mov.b64 %0, {%1, %2};" : "=l"(r) : "f"(x), "f"(y));
    return r;
}
__device__ __forceinline__ void fma2(uint64_t& d, uint64_t a, uint64_t b) {
    asm("fma.rn.f32x2 %0, %1, %2, %0;" : "+l"(d) : "l"(a), "l"(b));
}
__device__ __forceinline__ float2 unpack2(uint64_t v) {
    float2 f;
    asm("mov.b64 {%0, %1}, %2;" : "=f"(f.x), "=f"(f.y) : "l"(v));
    return f;
}

// ---------------- JAX threefry2x32 (partitionable semantics) --------------
__device__ __forceinline__ uint32_t rotl32(uint32_t v, int r) {
    return (v << r) | (v >> (32 - r));
}

__device__ __forceinline__ void tf2x32(uint32_t k0, uint32_t k1,
                                       uint32_t x0, uint32_t x1,
                                       uint32_t& o0, uint32_t& o1) {
    uint32_t ks2 = k0 ^ k1 ^ 0x1BD11BDAu;
    x0 += k0; x1 += k1;
#define TF_R(r) { x0 += x1; x1 = rotl32(x1, r); x1 ^= x0; }
    TF_R(13) TF_R(15) TF_R(26) TF_R(6)   x0 += k1;  x1 += ks2 + 1u;
    TF_R(17) TF_R(29) TF_R(16) TF_R(24)  x0 += ks2; x1 += k0 + 2u;
    TF_R(13) TF_R(15) TF_R(26) TF_R(6)   x0 += k0;  x1 += k1 + 3u;
    TF_R(17) TF_R(29) TF_R(16) TF_R(24)  x0 += k1;  x1 += ks2 + 4u;
    TF_R(13) TF_R(15) TF_R(26) TF_R(6)   x0 += ks2; x1 += k0 + 5u;
#undef TF_R
    o0 = x0; o1 = x1;
}

__device__ __forceinline__ bool drop_keep(uint32_t ka, uint32_t kb, uint32_t idx) {
    uint32_t a, b;
    tf2x32(ka, kb, 0u, idx, a, b);
    uint32_t bits = a ^ b;
    float u = __uint_as_float((bits >> 9) | 0x3F800000u) - 1.0f;
    return u < 0.8f;
}

// ---------------- shared-memory overlays ----------------------------------
struct SmemFc1  { float As[32][34]; float Bs[32][64]; };                  // 12544 B
struct SmemPnd  { float en[H]; float ed[H]; };                            //  8192 B
struct SmemNorm { float red[256]; };
struct SmemCp   { float As[16][64]; float Bs[16][64]; float base[64]; };
struct SmemXY   { float Hs[32][33]; float Ys[32][33]; float ws[32]; };
struct SmemXC   { float Hs[32][33]; float Cs[32][17]; float Ws[32][9]; };

#define SMEM_BYTES 12544

// ---------------- part: 1 + l2norm of one row ------------------------------
__device__ void part_norm(char* smem, int r,
                          const float* __restrict__ ye,
                          const float* __restrict__ ce) {
    SmemNorm& s = *reinterpret_cast<SmemNorm*>(smem);
    const float* src;
    float* dst;
    if (r < C) { src = ye + (size_t)r * H;        dst = g_y1 + (size_t)r * H; }
    else       { src = ce + (size_t)(r - C) * H;  dst = g_c1 + (size_t)(r - C) * H; }
    int t = threadIdx.x;
    float4 v = *reinterpret_cast<const float4*>(&src[t * 4]);
    s.red[t] = v.x * v.x + v.y * v.y + v.z * v.z + v.w * v.w;
    __syncthreads();
    for (int o = 128; o; o >>= 1) {
        if (t < o) s.red[t] += s.red[t + o];
        __syncthreads();
    }
    float n = fmaxf(sqrtf(s.red[0]), 1e-12f);
    dst[t * 4 + 0] = 1.0f + v.x / n;
    dst[t * 4 + 1] = 1.0f + v.y / n;
    dst[t * 4 + 2] = 1.0f + v.z / n;
    dst[t * 4 + 3] = 1.0f + v.w / n;
}

// ---------------- part: fc1 GEMM (f32x2) + bias + dropout ------------------
// tile: m=32 (batch), n=64 (H cols), k-chunk 32
__device__ void part_fc1(char* smem, int which, int n0, int m0,
                         const float* __restrict__ x,
                         const float* __restrict__ W,
                         const float* __restrict__ B,
                         float* __restrict__ out) {
    SmemFc1& s = *reinterpret_cast<SmemFc1*>(smem);
    const int tid = threadIdx.x;
    const int tx = tid % 16, ty = tid / 16;
    const int lr = tid / 8;          // 0..31
    const int lc = (tid % 8) * 4;    // 0..28
    uint64_t acc[2][2] = {};
    for (int k0 = 0; k0 < D; k0 += 32) {
        {
            float4 va = *reinterpret_cast<const float4*>(&x[(size_t)(m0 + lr) * D + k0 + lc]);
            s.As[lc + 0][lr] = va.x; s.As[lc + 1][lr] = va.y;
            s.As[lc + 2][lr] = va.z; s.As[lc + 3][lr] = va.w;
#pragma unroll
            for (int rr = 0; rr < 2; rr++) {
                int r = lr + rr * 32;
                float4 vb = *reinterpret_cast<const float4*>(&W[(size_t)(n0 + r) * D + k0 + lc]);
                s.Bs[lc + 0][r] = vb.x; s.Bs[lc + 1][r] = vb.y;
                s.Bs[lc + 2][r] = vb.z; s.Bs[lc + 3][r] = vb.w;
            }
        }
        __syncthreads();
#pragma unroll
        for (int kk = 0; kk < 32; kk++) {
            float a0 = s.As[kk][ty * 2 + 0];
            float a1 = s.As[kk][ty * 2 + 1];
            uint64_t ap0 = pack2(a0, a0);
            uint64_t ap1 = pack2(a1, a1);
            const uint64_t* bp = reinterpret_cast<const uint64_t*>(&s.Bs[kk][tx * 4]);
            uint64_t b0 = bp[0], b1 = bp[1];
            fma2(acc[0][0], ap0, b0); fma2(acc[0][1], ap0, b1);
            fma2(acc[1][0], ap1, b0); fma2(acc[1][1], ap1, b1);
        }
        __syncthreads();
    }
    uint32_t ka, kb;
    tf2x32(0u, 42u, 0u, (uint32_t)which, ka, kb);
#pragma unroll
    for (int i = 0; i < 2; i++) {
        int b = m0 + ty * 2 + i;
#pragma unroll
        for (int jp = 0; jp < 2; jp++) {
            float2 v = unpack2(acc[i][jp]);
            int col = n0 + tx * 4 + jp * 2;
            float h0 = v.x + B[col];
            float h1 = v.y + B[col + 1];
            uint32_t i0 = (uint32_t)(b * H + col);
            out[(size_t)b * H + col]     = drop_keep(ka, kb, i0)      ? h0 / 0.8f : 0.0f;
            out[(size_t)b * H + col + 1] = drop_keep(ka, kb, i0 + 1u) ? h1 / 0.8f : 0.0f;
        }
    }
}

// ---------------- part: stream concept_proj_w once --------------------------
// block: one concept n, 32 j rows. warp: 4 sequential contiguous rows,
// explicit 8x float4 batch loads per row (MLP=8).
__device__ void part_pnd(char* smem, int n, int jg,
                         const float* __restrict__ ce,
                         const float* __restrict__ W) {
    SmemPnd& s = *reinterpret_cast<SmemPnd*>(smem);
    const int tid = threadIdx.x;
    {
        int i = tid * 4;
        float4 ep = *reinterpret_cast<const float4*>(&ce[(size_t)n * H + i]);
        float4 en = *reinterpret_cast<const float4*>(&ce[(size_t)(NC + n) * H + i]);
        *reinterpret_cast<float4*>(&s.en[i]) = en;
        float4 ed = make_float4(ep.x - en.x, ep.y - en.y, ep.z - en.z, ep.w - en.w);
        *reinterpret_cast<float4*>(&s.ed[i]) = ed;
    }
    __syncthreads();
    const int w = tid >> 5, lane = tid & 31;
    const int jbase = jg * 32 + w * 4;
    const size_t rs = (size_t)NC * H;
    const float* Wr = W + (size_t)jbase * rs + (size_t)n * H + lane * 4;
#pragma unroll 1
    for (int r = 0; r < 4; r++) {
        const float* Wp = Wr + (size_t)r * rs;
        float4 wv[8];
#pragma unroll
        for (int c = 0; c < 8; c++)
            wv[c] = *reinterpret_cast<const float4*>(&Wp[c * 128]);
        float pn = 0.f, pd = 0.f;
#pragma unroll
        for (int c = 0; c < 8; c++) {
            int hh = c * 128 + lane * 4;
            float4 en = *reinterpret_cast<const float4*>(&s.en[hh]);
            float4 ed = *reinterpret_cast<const float4*>(&s.ed[hh]);
            pn += wv[c].x * en.x + wv[c].y * en.y + wv[c].z * en.z + wv[c].w * en.w;
            pd += wv[c].x * ed.x + wv[c].y * ed.y + wv[c].z * ed.z + wv[c].w * ed.w;
        }
#pragma unroll
        for (int off = 16; off; off >>= 1) {
            pn += __shfl_down_sync(0xFFFFFFFFu, pn, off);
            pd += __shfl_down_sync(0xFFFFFFFFu, pd, off);
        }
        if (lane == 0) {
            g_pn[n * H + jbase + r] = pn;
            g_pd[n * H + jbase + r] = pd;
        }
    }
}

// ---------------- part: c_proj = (bias + sum_n pn) + gt @ pd ----------------
__device__ void part_cproj(char* smem, int j0, int m0,
                           const int* __restrict__ cgt,
                           const float* __restrict__ bias) {
    SmemCp& s = *reinterpret_cast<SmemCp*>(smem);
    const int tid = threadIdx.x;
    {
        int col = j0 + (tid & 63);
        if (tid < 64) s.base[tid] = bias[col];
        __syncthreads();
        int nb = (tid >> 6) * 28;
        float part = 0.f;
#pragma unroll 4
        for (int n = nb; n < nb + 28; n++) part += g_pn[n * H + col];
        atomicAdd(&s.base[tid & 63], part);
    }
    const int tx = tid % 16, ty = tid / 16;
    float acc[4][4] = {};
    for (int k0 = 0; k0 < NC; k0 += 16) {
        __syncthreads();
        {
            int r = tid / 4;
            int c = (tid % 4) * 4;
            int b = m0 + r;
#pragma unroll
            for (int q = 0; q < 4; q++)
                s.As[c + q][r] = (cgt[(size_t)b * NC + k0 + c + q] == 1) ? 1.0f : 0.0f;
        }
        {
            int kk = tid / 16;
            int j4 = (tid % 16) * 4;
            float4 v = *reinterpret_cast<const float4*>(&g_pd[(size_t)(k0 + kk) * H + j0 + j4]);
            *reinterpret_cast<float4*>(&s.Bs[kk][j4]) = v;
        }
        __syncthreads();
#pragma unroll
        for (int kk = 0; kk < 16; kk++) {
            float4 a = *reinterpret_cast<const float4*>(&s.As[kk][ty * 4]);
            float4 b = *reinterpret_cast<const float4*>(&s.Bs[kk][tx * 4]);
            float av[4] = {a.x, a.y, a.z, a.w};
            float bv[4] = {b.x, b.y, b.z, b.w};
#pragma unroll
            for (int i = 0; i < 4; i++)
#pragma unroll
                for (int j = 0; j < 4; j++)
                    acc[i][j] = fmaf(av[i], bv[j], acc[i][j]);
        }
    }
#pragma unroll
    for (int i = 0; i < 4; i++) {
        int b = m0 + ty * 4 + i;
#pragma unroll
        for (int j = 0; j < 4; j++) {
            int col = j0 + tx * 4 + j;
            g_cproj[(size_t)b * H + col] = acc[i][j] + s.base[tx * 4 + j];
        }
    }
}

// ---------------- part: xy / cy energy --------------------------------------
__device__ void part_xycy(char* smem, int c0, int b0,
                          const float* __restrict__ A,
                          const float* __restrict__ clsw,
                          float bias,
                          float* __restrict__ out) {
    SmemXY& s = *reinterpret_cast<SmemXY*>(smem);
    const int tid = threadIdx.x;
    const int tx = tid % 16, ty = tid / 16;
    const int lr = tid / 8;
    const int lc = (tid % 8) * 4;
    float acc[2][2] = {};
    for (int k0 = 0; k0 < H; k0 += 32) {
        {
            float4 v = *reinterpret_cast<const float4*>(&A[(size_t)(b0 + lr) * H + k0 + lc]);
            s.Hs[lc + 0][lr] = v.x; s.Hs[lc + 1][lr] = v.y;
            s.Hs[lc + 2][lr] = v.z; s.Hs[lc + 3][lr] = v.w;
            int cr = c0 + lr; if (cr > C - 1) cr = C - 1;
            float4 u = *reinterpret_cast<const float4*>(&g_y1[(size_t)cr * H + k0 + lc]);
            s.Ys[lc + 0][lr] = u.x; s.Ys[lc + 1][lr] = u.y;
            s.Ys[lc + 2][lr] = u.z; s.Ys[lc + 3][lr] = u.w;
            if (tid < 32) s.ws[tid] = clsw[k0 + tid];
        }
        __syncthreads();
#pragma unroll
        for (int kk = 0; kk < 32; kk++) {
            float a0 = s.Hs[kk][ty * 2 + 0];
            float a1 = s.Hs[kk][ty * 2 + 1];
            float y0 = s.Ys[kk][tx * 2 + 0];
            float y1v = s.Ys[kk][tx * 2 + 1];
            float w = s.ws[kk];
            acc[0][0] = fmaf(fmaxf(a0 * y0, 0.f), w, acc[0][0]);
            acc[0][1] = fmaf(fmaxf(a0 * y1v, 0.f), w, acc[0][1]);
            acc[1][0] = fmaf(fmaxf(a1 * y0, 0.f), w, acc[1][0]);
            acc[1][1] = fmaf(fmaxf(a1 * y1v, 0.f), w, acc[1][1]);
        }
        __syncthreads();
    }
#pragma unroll
    for (int i = 0; i < 2; i++) {
        int b = b0 + ty * 2 + i;
#pragma unroll
        for (int j = 0; j < 2; j++) {
            int c = c0 + tx * 2 + j;
            if (c < C) out[(size_t)b * C + c] = acc[i][j] + bias;
        }
    }
}

// ---------------- part: xc energy -------------------------------------------
__device__ void part_xc(char* smem, int n0, int b0,
                        const float* __restrict__ xcw,
                        const float* __restrict__ xcb,
                        float* __restrict__ out) {
    SmemXC& s = *reinterpret_cast<SmemXC*>(smem);
    const int tid = threadIdx.x;
    const int tx = tid % 8;
    const int ty = tid / 8;
    const int lr = tid / 8;
    const int lc = (tid % 8) * 4;
    float acc0 = 0.f, acc1 = 0.f;
    for (int k0 = 0; k0 < H; k0 += 32) {
        {
            float4 v = *reinterpret_cast<const float4*>(&g_hxc[(size_t)(b0 + lr) * H + k0 + lc]);
            s.Hs[lc + 0][lr] = v.x; s.Hs[lc + 1][lr] = v.y;
            s.Hs[lc + 2][lr] = v.z; s.Hs[lc + 3][lr] = v.w;
        }
        {
            int loc = tid / 16;
            int kk = (tid % 16) * 2;
            int nl = loc >> 1, sx = loc & 1;
            int row = sx * NC + (n0 + nl);
            float2 v = *reinterpret_cast<const float2*>(&g_c1[(size_t)row * H + k0 + kk]);
            s.Cs[kk + 0][nl * 2 + sx] = v.x;
            s.Cs[kk + 1][nl * 2 + sx] = v.y;
        }
        {
            int nl = tid / 32;
            int kk = tid % 32;
            s.Ws[kk][nl] = xcw[(size_t)(n0 + nl) * H + k0 + kk];
        }
        __syncthreads();
#pragma unroll
        for (int kk = 0; kk < 32; kk++) {
            float h = s.Hs[kk][ty];
            float w = s.Ws[kk][tx];
            float cp = s.Cs[kk][tx * 2 + 0];
            float cn = s.Cs[kk][tx * 2 + 1];
            acc0 = fmaf(fmaxf(h * cp, 0.f), w, acc0);
            acc1 = fmaf(fmaxf(h * cn, 0.f), w, acc1);
        }
        __syncthreads();
    }
    int b = b0 + ty, n = n0 + tx;
    float bb = xcb[n];
    size_t base = (size_t)(2 * BS * C) + (size_t)b * (NC * 2) + n * 2;
    out[base + 0] = acc0 + bb;
    out[base + 1] = acc1 + bb;
}

// ================= launch 1: fc1 + norm + pnd (overlapped) ==================
#define L1_FC1   256                          // 2 x (8 m-tiles x 16 n-tiles)
#define L1_NORM  (C + 2 * NC)                 // 424
#define L1_PND   (NC * 32)                    // 3584 (32-j groups)
#define L1_GRID  (L1_FC1 + L1_NORM + L1_PND)

__global__ __launch_bounds__(256, 5) void k_main(const float* __restrict__ x,
                                                 const float* __restrict__ ye,
                                                 const float* __restrict__ ce,
                                                 const float* __restrict__ w0,
                                                 const float* __restrict__ b0,
                                                 const float* __restrict__ w1,
                                                 const float* __restrict__ b1,
                                                 const float* __restrict__ cpw) {
    __shared__ __align__(16) char smem[SMEM_BYTES];
    int bid = blockIdx.x;
    if (bid < L1_FC1) {
        int which = bid >> 7;
        int rem = bid & 127;
        part_fc1(smem, which, (rem % 16) * 64, (rem / 16) * 32, x,
                 which ? w1 : w0, which ? b1 : b0, which ? g_hxc : g_hxy);
    } else if (bid < L1_FC1 + L1_NORM) {
        part_norm(smem, bid - L1_FC1, ye, ce);
    } else {
        int p = bid - (L1_FC1 + L1_NORM);
        part_pnd(smem, p % NC, p / NC, ce, cpw);
    }
}

// ================= launch 2: cproj + xy-energy + xc-energy ==================
#define L2_CP   (16 * 4)              // 64
#define L2_XY   (7 * 8)               // 56
#define L2_XC   (14 * 8)              // 112
#define L2_GRID (L2_CP + L2_XY + L2_XC)

__global__ __launch_bounds__(256) void k_mid(const int* __restrict__ cgt,
                                             const float* __restrict__ cpb,
                                             const float* __restrict__ clsxy_w,
                                             const float* __restrict__ clsxy_b,
                                             const float* __restrict__ xcw,
                                             const float* __restrict__ xcb,
                                             float* __restrict__ out) {
    __shared__ __align__(16) char smem[SMEM_BYTES];
    int bid = blockIdx.x;
    if (bid < L2_CP) {
        part_cproj(smem, (bid % 16) * 64, (bid / 16) * 64, cgt, cpb);
    } else if (bid < L2_CP + L2_XY) {
        int p = bid - L2_CP;
        part_xycy(smem, (p % 7) * 32, (p / 7) * 32, g_hxy, clsxy_w, clsxy_b[0], out);
    } else {
        int p = bid - (L2_CP + L2_XY);
        part_xc(smem, (p % 14) * 8, (p / 14) * 32, xcw, xcb, out);
    }
}

// ================= launch 3: cy-energy ======================================
__global__ __launch_bounds__(256) void k_cy(const float* __restrict__ clscy_w,
                                            const float* __restrict__ clscy_b,
                                            float* __restrict__ out) {
    __shared__ __align__(16) char smem[SMEM_BYTES];
    int bid = blockIdx.x;
    part_xycy(smem, (bid % 7) * 32, (bid / 7) * 32, g_cproj, clscy_w, clscy_b[0],
              out + (size_t)BS * C);
}

// ---------------- launch ----------------------------------------------------
extern "C" void kernel_launch(void* const* d_in, const int* in_sizes, int n_in,
                              void* d_out, int out_size) {
    (void)in_sizes; (void)n_in; (void)out_size;
    const float* x       = (const float*)d_in[0];
    const int*   c_gt    = (const int*)d_in[1];
    const float* y_emb   = (const float*)d_in[2];
    const float* c_emb   = (const float*)d_in[3];
    const float* xy_w    = (const float*)d_in[4];
    const float* xy_b    = (const float*)d_in[5];
    const float* xc_w1   = (const float*)d_in[6];
    const float* xc_b1   = (const float*)d_in[7];
    const float* clsxy_w = (const float*)d_in[8];
    const float* clsxy_b = (const float*)d_in[9];
    const float* clscy_w = (const float*)d_in[10];
    const float* clscy_b = (const float*)d_in[11];
    const float* xcw     = (const float*)d_in[12];
    const float* xcb     = (const float*)d_in[13];
    const float* cpw     = (const float*)d_in[14];
    const float* cpb     = (const float*)d_in[15];
    float* out = (float*)d_out;

    k_main<<<L1_GRID, 256>>>(x, y_emb, c_emb, xy_w, xy_b, xc_w1, xc_b1, cpw);
    k_mid<<<L2_GRID, 256>>>(c_gt, cpb, clsxy_w, clsxy_b, xcw, xcb, out);
    k_cy<<<7 * 8, 256>>>(clscy_w, clscy_b, out);
}

// round 6
// speedup vs baseline: 1.7126x; 1.1688x over previous
#include <cuda_runtime.h>
#include <cstdint>

#define BS 256
#define D  2048
#define H  1024
#define C  200
#define NC 112

// ---------------- scratch (static device allocations only) ----------------
__device__ float g_y1[C * H];
__device__ float g_c1[2 * NC * H];
__device__ float g_hxy[BS * H];
__device__ float g_hxc[BS * H];
__device__ float g_pn[NC * H];
__device__ float g_pd[NC * H];
__device__ float g_cproj[BS * H];

// ---------------- packed f32x2 helpers -------------------------------------
__device__ __forceinline__ uint64_t pack2(float x, float y) {
    uint64_t r;
    asm("mov.b64 %0, {%1, %2};" : "=l"(r) : "f"(x), "f"(y));
    return r;
}
__device__ __forceinline__ void fma2(uint64_t& d, uint64_t a, uint64_t b) {
    asm("fma.rn.f32x2 %0, %1, %2, %0;" : "+l"(d) : "l"(a), "l"(b));
}
__device__ __forceinline__ float2 unpack2(uint64_t v) {
    float2 f;
    asm("mov.b64 {%0, %1}, %2;" : "=f"(f.x), "=f"(f.y) : "l"(v));
    return f;
}

// ---------------- JAX threefry2x32 (partitionable semantics) --------------
__device__ __forceinline__ uint32_t rotl32(uint32_t v, int r) {
    return (v << r) | (v >> (32 - r));
}

__device__ __forceinline__ void tf2x32(uint32_t k0, uint32_t k1,
                                       uint32_t x0, uint32_t x1,
                                       uint32_t& o0, uint32_t& o1) {
    uint32_t ks2 = k0 ^ k1 ^ 0x1BD11BDAu;
    x0 += k0; x1 += k1;
#define TF_R(r) { x0 += x1; x1 = rotl32(x1, r); x1 ^= x0; }
    TF_R(13) TF_R(15) TF_R(26) TF_R(6)   x0 += k1;  x1 += ks2 + 1u;
    TF_R(17) TF_R(29) TF_R(16) TF_R(24)  x0 += ks2; x1 += k0 + 2u;
    TF_R(13) TF_R(15) TF_R(26) TF_R(6)   x0 += k0;  x1 += k1 + 3u;
    TF_R(17) TF_R(29) TF_R(16) TF_R(24)  x0 += k1;  x1 += ks2 + 4u;
    TF_R(13) TF_R(15) TF_R(26) TF_R(6)   x0 += ks2; x1 += k0 + 5u;
#undef TF_R
    o0 = x0; o1 = x1;
}

__device__ __forceinline__ bool drop_keep(uint32_t ka, uint32_t kb, uint32_t idx) {
    uint32_t a, b;
    tf2x32(ka, kb, 0u, idx, a, b);
    uint32_t bits = a ^ b;
    float u = __uint_as_float((bits >> 9) | 0x3F800000u) - 1.0f;
    return u < 0.8f;
}

// ---------------- shared-memory overlays ----------------------------------
struct SmemFc1  { float As[32][34]; float Bs[32][64]; };                  // 12544 B
struct SmemNorm { float red[256]; };
struct SmemCp   { float As[16][64]; float Bs[16][64]; float base[64]; };
struct SmemXY   { float Hs[32][33]; float Ys[32][33]; float ws[32]; };
struct SmemXC   { float Hs[32][33]; float Cs[32][17]; float Ws[32][9]; };

#define SMEM_BYTES 12544

// ---------------- part: 1 + l2norm of one row ------------------------------
__device__ void part_norm(char* smem, int r,
                          const float* __restrict__ ye,
                          const float* __restrict__ ce) {
    SmemNorm& s = *reinterpret_cast<SmemNorm*>(smem);
    const float* src;
    float* dst;
    if (r < C) { src = ye + (size_t)r * H;        dst = g_y1 + (size_t)r * H; }
    else       { src = ce + (size_t)(r - C) * H;  dst = g_c1 + (size_t)(r - C) * H; }
    int t = threadIdx.x;
    float4 v = *reinterpret_cast<const float4*>(&src[t * 4]);
    s.red[t] = v.x * v.x + v.y * v.y + v.z * v.z + v.w * v.w;
    __syncthreads();
    for (int o = 128; o; o >>= 1) {
        if (t < o) s.red[t] += s.red[t + o];
        __syncthreads();
    }
    float n = fmaxf(sqrtf(s.red[0]), 1e-12f);
    dst[t * 4 + 0] = 1.0f + v.x / n;
    dst[t * 4 + 1] = 1.0f + v.y / n;
    dst[t * 4 + 2] = 1.0f + v.z / n;
    dst[t * 4 + 3] = 1.0f + v.w / n;
}

// ---------------- part: fc1 GEMM (f32x2) + bias + dropout ------------------
// tile: m=32 (batch), n=64 (H cols), k-chunk 32
__device__ void part_fc1(char* smem, int which, int n0, int m0,
                         const float* __restrict__ x,
                         const float* __restrict__ W,
                         const float* __restrict__ B,
                         float* __restrict__ out) {
    SmemFc1& s = *reinterpret_cast<SmemFc1*>(smem);
    const int tid = threadIdx.x;
    const int tx = tid % 16, ty = tid / 16;
    const int lr = tid / 8;          // 0..31
    const int lc = (tid % 8) * 4;    // 0..28
    uint64_t acc[2][2] = {};
    for (int k0 = 0; k0 < D; k0 += 32) {
        {
            float4 va = *reinterpret_cast<const float4*>(&x[(size_t)(m0 + lr) * D + k0 + lc]);
            s.As[lc + 0][lr] = va.x; s.As[lc + 1][lr] = va.y;
            s.As[lc + 2][lr] = va.z; s.As[lc + 3][lr] = va.w;
#pragma unroll
            for (int rr = 0; rr < 2; rr++) {
                int r = lr + rr * 32;
                float4 vb = *reinterpret_cast<const float4*>(&W[(size_t)(n0 + r) * D + k0 + lc]);
                s.Bs[lc + 0][r] = vb.x; s.Bs[lc + 1][r] = vb.y;
                s.Bs[lc + 2][r] = vb.z; s.Bs[lc + 3][r] = vb.w;
            }
        }
        __syncthreads();
#pragma unroll
        for (int kk = 0; kk < 32; kk++) {
            float a0 = s.As[kk][ty * 2 + 0];
            float a1 = s.As[kk][ty * 2 + 1];
            uint64_t ap0 = pack2(a0, a0);
            uint64_t ap1 = pack2(a1, a1);
            const uint64_t* bp = reinterpret_cast<const uint64_t*>(&s.Bs[kk][tx * 4]);
            uint64_t b0 = bp[0], b1 = bp[1];
            fma2(acc[0][0], ap0, b0); fma2(acc[0][1], ap0, b1);
            fma2(acc[1][0], ap1, b0); fma2(acc[1][1], ap1, b1);
        }
        __syncthreads();
    }
    uint32_t ka, kb;
    tf2x32(0u, 42u, 0u, (uint32_t)which, ka, kb);
#pragma unroll
    for (int i = 0; i < 2; i++) {
        int b = m0 + ty * 2 + i;
#pragma unroll
        for (int jp = 0; jp < 2; jp++) {
            float2 v = unpack2(acc[i][jp]);
            int col = n0 + tx * 4 + jp * 2;
            float h0 = v.x + B[col];
            float h1 = v.y + B[col + 1];
            uint32_t i0 = (uint32_t)(b * H + col);
            out[(size_t)b * H + col]     = drop_keep(ka, kb, i0)      ? h0 / 0.8f : 0.0f;
            out[(size_t)b * H + col + 1] = drop_keep(ka, kb, i0 + 1u) ? h1 / 0.8f : 0.0f;
        }
    }
}

// ---------------- part: stream concept_proj_w once (register-resident e) ----
// block: one concept n, 32 j rows. warp: 4 sequential contiguous rows.
// ep/en held in registers -> inner loop is pure LDG.128 + FFMA (no LDS).
__device__ void part_pnd(int n, int jg,
                         const float* __restrict__ ce,
                         const float* __restrict__ W) {
    const int tid = threadIdx.x;
    const int w = tid >> 5, lane = tid & 31;
    const int jbase = jg * 32 + w * 4;
    const size_t rs = (size_t)NC * H;
    // preload this lane's e-slices (L2-hot: 32 blocks share each n)
    float4 ep[8], en[8];
    {
        const float* epg = ce + (size_t)n * H + lane * 4;
        const float* eng = ce + (size_t)(NC + n) * H + lane * 4;
#pragma unroll
        for (int c = 0; c < 8; c++) {
            ep[c] = *reinterpret_cast<const float4*>(&epg[c * 128]);
            en[c] = *reinterpret_cast<const float4*>(&eng[c * 128]);
        }
    }
    const float* Wr = W + (size_t)jbase * rs + (size_t)n * H + lane * 4;
#pragma unroll 1
    for (int r = 0; r < 4; r++) {
        const float* Wp = Wr + (size_t)r * rs;
        float4 wv[8];
#pragma unroll
        for (int c = 0; c < 8; c++)
            wv[c] = *reinterpret_cast<const float4*>(&Wp[c * 128]);
        float ap = 0.f, an = 0.f;
#pragma unroll
        for (int c = 0; c < 8; c++) {
            ap += wv[c].x * ep[c].x + wv[c].y * ep[c].y + wv[c].z * ep[c].z + wv[c].w * ep[c].w;
            an += wv[c].x * en[c].x + wv[c].y * en[c].y + wv[c].z * en[c].z + wv[c].w * en[c].w;
        }
#pragma unroll
        for (int off = 16; off; off >>= 1) {
            ap += __shfl_down_sync(0xFFFFFFFFu, ap, off);
            an += __shfl_down_sync(0xFFFFFFFFu, an, off);
        }
        if (lane == 0) {
            g_pn[n * H + jbase + r] = an;
            g_pd[n * H + jbase + r] = ap - an;
        }
    }
}

// ---------------- part: c_proj = (bias + sum_n pn) + gt @ pd ----------------
__device__ void part_cproj(char* smem, int j0, int m0,
                           const int* __restrict__ cgt,
                           const float* __restrict__ bias) {
    SmemCp& s = *reinterpret_cast<SmemCp*>(smem);
    const int tid = threadIdx.x;
    {
        int col = j0 + (tid & 63);
        if (tid < 64) s.base[tid] = bias[col];
        __syncthreads();
        int nb = (tid >> 6) * 28;
        float part = 0.f;
#pragma unroll 4
        for (int n = nb; n < nb + 28; n++) part += g_pn[n * H + col];
        atomicAdd(&s.base[tid & 63], part);
    }
    const int tx = tid % 16, ty = tid / 16;
    float acc[4][4] = {};
    for (int k0 = 0; k0 < NC; k0 += 16) {
        __syncthreads();
        {
            int r = tid / 4;
            int c = (tid % 4) * 4;
            int b = m0 + r;
#pragma unroll
            for (int q = 0; q < 4; q++)
                s.As[c + q][r] = (cgt[(size_t)b * NC + k0 + c + q] == 1) ? 1.0f : 0.0f;
        }
        {
            int kk = tid / 16;
            int j4 = (tid % 16) * 4;
            float4 v = *reinterpret_cast<const float4*>(&g_pd[(size_t)(k0 + kk) * H + j0 + j4]);
            *reinterpret_cast<float4*>(&s.Bs[kk][j4]) = v;
        }
        __syncthreads();
#pragma unroll
        for (int kk = 0; kk < 16; kk++) {
            float4 a = *reinterpret_cast<const float4*>(&s.As[kk][ty * 4]);
            float4 b = *reinterpret_cast<const float4*>(&s.Bs[kk][tx * 4]);
            float av[4] = {a.x, a.y, a.z, a.w};
            float bv[4] = {b.x, b.y, b.z, b.w};
#pragma unroll
            for (int i = 0; i < 4; i++)
#pragma unroll
                for (int j = 0; j < 4; j++)
                    acc[i][j] = fmaf(av[i], bv[j], acc[i][j]);
        }
    }
#pragma unroll
    for (int i = 0; i < 4; i++) {
        int b = m0 + ty * 4 + i;
#pragma unroll
        for (int j = 0; j < 4; j++) {
            int col = j0 + tx * 4 + j;
            g_cproj[(size_t)b * H + col] = acc[i][j] + s.base[tx * 4 + j];
        }
    }
}

// ---------------- part: xy / cy energy --------------------------------------
__device__ void part_xycy(char* smem, int c0, int b0,
                          const float* __restrict__ A,
                          const float* __restrict__ clsw,
                          float bias,
                          float* __restrict__ out) {
    SmemXY& s = *reinterpret_cast<SmemXY*>(smem);
    const int tid = threadIdx.x;
    const int tx = tid % 16, ty = tid / 16;
    const int lr = tid / 8;
    const int lc = (tid % 8) * 4;
    float acc[2][2] = {};
    for (int k0 = 0; k0 < H; k0 += 32) {
        {
            float4 v = *reinterpret_cast<const float4*>(&A[(size_t)(b0 + lr) * H + k0 + lc]);
            s.Hs[lc + 0][lr] = v.x; s.Hs[lc + 1][lr] = v.y;
            s.Hs[lc + 2][lr] = v.z; s.Hs[lc + 3][lr] = v.w;
            int cr = c0 + lr; if (cr > C - 1) cr = C - 1;
            float4 u = *reinterpret_cast<const float4*>(&g_y1[(size_t)cr * H + k0 + lc]);
            s.Ys[lc + 0][lr] = u.x; s.Ys[lc + 1][lr] = u.y;
            s.Ys[lc + 2][lr] = u.z; s.Ys[lc + 3][lr] = u.w;
            if (tid < 32) s.ws[tid] = clsw[k0 + tid];
        }
        __syncthreads();
#pragma unroll
        for (int kk = 0; kk < 32; kk++) {
            float a0 = s.Hs[kk][ty * 2 + 0];
            float a1 = s.Hs[kk][ty * 2 + 1];
            float y0 = s.Ys[kk][tx * 2 + 0];
            float y1v = s.Ys[kk][tx * 2 + 1];
            float w = s.ws[kk];
            acc[0][0] = fmaf(fmaxf(a0 * y0, 0.f), w, acc[0][0]);
            acc[0][1] = fmaf(fmaxf(a0 * y1v, 0.f), w, acc[0][1]);
            acc[1][0] = fmaf(fmaxf(a1 * y0, 0.f), w, acc[1][0]);
            acc[1][1] = fmaf(fmaxf(a1 * y1v, 0.f), w, acc[1][1]);
        }
        __syncthreads();
    }
#pragma unroll
    for (int i = 0; i < 2; i++) {
        int b = b0 + ty * 2 + i;
#pragma unroll
        for (int j = 0; j < 2; j++) {
            int c = c0 + tx * 2 + j;
            if (c < C) out[(size_t)b * C + c] = acc[i][j] + bias;
        }
    }
}

// ---------------- part: xc energy -------------------------------------------
__device__ void part_xc(char* smem, int n0, int b0,
                        const float* __restrict__ xcw,
                        const float* __restrict__ xcb,
                        float* __restrict__ out) {
    SmemXC& s = *reinterpret_cast<SmemXC*>(smem);
    const int tid = threadIdx.x;
    const int tx = tid % 8;
    const int ty = tid / 8;
    const int lr = tid / 8;
    const int lc = (tid % 8) * 4;
    float acc0 = 0.f, acc1 = 0.f;
    for (int k0 = 0; k0 < H; k0 += 32) {
        {
            float4 v = *reinterpret_cast<const float4*>(&g_hxc[(size_t)(b0 + lr) * H + k0 + lc]);
            s.Hs[lc + 0][lr] = v.x; s.Hs[lc + 1][lr] = v.y;
            s.Hs[lc + 2][lr] = v.z; s.Hs[lc + 3][lr] = v.w;
        }
        {
            int loc = tid / 16;
            int kk = (tid % 16) * 2;
            int nl = loc >> 1, sx = loc & 1;
            int row = sx * NC + (n0 + nl);
            float2 v = *reinterpret_cast<const float2*>(&g_c1[(size_t)row * H + k0 + kk]);
            s.Cs[kk + 0][nl * 2 + sx] = v.x;
            s.Cs[kk + 1][nl * 2 + sx] = v.y;
        }
        {
            int nl = tid / 32;
            int kk = tid % 32;
            s.Ws[kk][nl] = xcw[(size_t)(n0 + nl) * H + k0 + kk];
        }
        __syncthreads();
#pragma unroll
        for (int kk = 0; kk < 32; kk++) {
            float h = s.Hs[kk][ty];
            float w = s.Ws[kk][tx];
            float cp = s.Cs[kk][tx * 2 + 0];
            float cn = s.Cs[kk][tx * 2 + 1];
            acc0 = fmaf(fmaxf(h * cp, 0.f), w, acc0);
            acc1 = fmaf(fmaxf(h * cn, 0.f), w, acc1);
        }
        __syncthreads();
    }
    int b = b0 + ty, n = n0 + tx;
    float bb = xcb[n];
    size_t base = (size_t)(2 * BS * C) + (size_t)b * (NC * 2) + n * 2;
    out[base + 0] = acc0 + bb;
    out[base + 1] = acc1 + bb;
}

// ================= launch 1: fc1 + norm + pnd (overlapped) ==================
#define L1_FC1   256                          // 2 x (8 m-tiles x 16 n-tiles)
#define L1_NORM  (C + 2 * NC)                 // 424
#define L1_PND   (NC * 32)                    // 3584 (32-j groups)
#define L1_GRID  (L1_FC1 + L1_NORM + L1_PND)

__global__ __launch_bounds__(256, 2) void k_main(const float* __restrict__ x,
                                                 const float* __restrict__ ye,
                                                 const float* __restrict__ ce,
                                                 const float* __restrict__ w0,
                                                 const float* __restrict__ b0,
                                                 const float* __restrict__ w1,
                                                 const float* __restrict__ b1,
                                                 const float* __restrict__ cpw) {
    __shared__ __align__(16) char smem[SMEM_BYTES];
    int bid = blockIdx.x;
    if (bid < L1_FC1) {
        int which = bid >> 7;
        int rem = bid & 127;
        part_fc1(smem, which, (rem % 16) * 64, (rem / 16) * 32, x,
                 which ? w1 : w0, which ? b1 : b0, which ? g_hxc : g_hxy);
    } else if (bid < L1_FC1 + L1_NORM) {
        part_norm(smem, bid - L1_FC1, ye, ce);
    } else {
        int p = bid - (L1_FC1 + L1_NORM);
        part_pnd(p % NC, p / NC, ce, cpw);
    }
}

// ================= launch 2: cproj + xy-energy + xc-energy ==================
#define L2_CP   (16 * 4)              // 64
#define L2_XY   (7 * 8)               // 56
#define L2_XC   (14 * 8)              // 112
#define L2_GRID (L2_CP + L2_XY + L2_XC)

__global__ __launch_bounds__(256) void k_mid(const int* __restrict__ cgt,
                                             const float* __restrict__ cpb,
                                             const float* __restrict__ clsxy_w,
                                             const float* __restrict__ clsxy_b,
                                             const float* __restrict__ xcw,
                                             const float* __restrict__ xcb,
                                             float* __restrict__ out) {
    __shared__ __align__(16) char smem[SMEM_BYTES];
    int bid = blockIdx.x;
    if (bid < L2_CP) {
        part_cproj(smem, (bid % 16) * 64, (bid / 16) * 64, cgt, cpb);
    } else if (bid < L2_CP + L2_XY) {
        int p = bid - L2_CP;
        part_xycy(smem, (p % 7) * 32, (p / 7) * 32, g_hxy, clsxy_w, clsxy_b[0], out);
    } else {
        int p = bid - (L2_CP + L2_XY);
        part_xc(smem, (p % 14) * 8, (p / 14) * 32, xcw, xcb, out);
    }
}

// ================= launch 3: cy-energy ======================================
__global__ __launch_bounds__(256) void k_cy(const float* __restrict__ clscy_w,
                                            const float* __restrict__ clscy_b,
                                            float* __restrict__ out) {
    __shared__ __align__(16) char smem[SMEM_BYTES];
    int bid = blockIdx.x;
    part_xycy(smem, (bid % 7) * 32, (bid / 7) * 32, g_cproj, clscy_w, clscy_b[0],
              out + (size_t)BS * C);
}

// ---------------- launch ----------------------------------------------------
extern "C" void kernel_launch(void* const* d_in, const int* in_sizes, int n_in,
                              void* d_out, int out_size) {
    (void)in_sizes; (void)n_in; (void)out_size;
    const float* x       = (const float*)d_in[0];
    const int*   c_gt    = (const int*)d_in[1];
    const float* y_emb   = (const float*)d_in[2];
    const float* c_emb   = (const float*)d_in[3];
    const float* xy_w    = (const float*)d_in[4];
    const float* xy_b    = (const float*)d_in[5];
    const float* xc_w1   = (const float*)d_in[6];
    const float* xc_b1   = (const float*)d_in[7];
    const float* clsxy_w = (const float*)d_in[8];
    const float* clsxy_b = (const float*)d_in[9];
    const float* clscy_w = (const float*)d_in[10];
    const float* clscy_b = (const float*)d_in[11];
    const float* xcw     = (const float*)d_in[12];
    const float* xcb     = (const float*)d_in[13];
    const float* cpw     = (const float*)d_in[14];
    const float* cpb     = (const float*)d_in[15];
    float* out = (float*)d_out;

    k_main<<<L1_GRID, 256>>>(x, y_emb, c_emb, xy_w, xy_b, xc_w1, xc_b1, cpw);
    k_mid<<<L2_GRID, 256>>>(c_gt, cpb, clsxy_w, clsxy_b, xcw, xcb, out);
    k_cy<<<7 * 8, 256>>>(clscy_w, clscy_b, out);
}

// round 9
// speedup vs baseline: 1.8896x; 1.1034x over previous
#include <cuda_runtime.h>
#include <cstdint>

#define BS 256
#define D  2048
#define H  1024
#define C  200
#define NC 112

// ---------------- scratch (static device allocations only) ----------------
__device__ float g_y1[C * H];
__device__ float g_c1[2 * NC * H];
__device__ float g_hxy[BS * H];
__device__ float g_hxc[BS * H];
__device__ float g_pn[NC * H];
__device__ float g_pd[NC * H];
__device__ float g_cproj[BS * H];

// ---------------- packed f32x2 helpers -------------------------------------
__device__ __forceinline__ uint64_t pack2(float x, float y) {
    uint64_t r;
    asm("mov.b64 %0, {%1, %2};" : "=l"(r) : "f"(x), "f"(y));
    return r;
}
__device__ __forceinline__ void fma2(uint64_t& d, uint64_t a, uint64_t b) {
    asm("fma.rn.f32x2 %0, %1, %2, %0;" : "+l"(d) : "l"(a), "l"(b));
}
__device__ __forceinline__ float2 unpack2(uint64_t v) {
    float2 f;
    asm("mov.b64 {%0, %1}, %2;" : "=f"(f.x), "=f"(f.y) : "l"(v));
    return f;
}

// ---------------- JAX threefry2x32 (partitionable semantics) --------------
__device__ __forceinline__ uint32_t rotl32(uint32_t v, int r) {
    return (v << r) | (v >> (32 - r));
}

__device__ __forceinline__ void tf2x32(uint32_t k0, uint32_t k1,
                                       uint32_t x0, uint32_t x1,
                                       uint32_t& o0, uint32_t& o1) {
    uint32_t ks2 = k0 ^ k1 ^ 0x1BD11BDAu;
    x0 += k0; x1 += k1;
#define TF_R(r) { x0 += x1; x1 = rotl32(x1, r); x1 ^= x0; }
    TF_R(13) TF_R(15) TF_R(26) TF_R(6)   x0 += k1;  x1 += ks2 + 1u;
    TF_R(17) TF_R(29) TF_R(16) TF_R(24)  x0 += ks2; x1 += k0 + 2u;
    TF_R(13) TF_R(15) TF_R(26) TF_R(6)   x0 += k0;  x1 += k1 + 3u;
    TF_R(17) TF_R(29) TF_R(16) TF_R(24)  x0 += k1;  x1 += ks2 + 4u;
    TF_R(13) TF_R(15) TF_R(26) TF_R(6)   x0 += ks2; x1 += k0 + 5u;
#undef TF_R
    o0 = x0; o1 = x1;
}

__device__ __forceinline__ bool drop_keep(uint32_t ka, uint32_t kb, uint32_t idx) {
    uint32_t a, b;
    tf2x32(ka, kb, 0u, idx, a, b);
    uint32_t bits = a ^ b;
    float u = __uint_as_float((bits >> 9) | 0x3F800000u) - 1.0f;
    return u < 0.8f;
}

// ---------------- shared-memory overlays ----------------------------------
struct SmemFc1  { float As[32][68]; float Bs[32][68]; };                   // 17408 B
struct SmemNorm { float red[256]; };
struct SmemCp   { float As[16][64]; float Bs[16][64]; float base[64]; };
struct SmemXY   { float Hs[64][17]; float Ys[64][33]; float ws[64]; };     // 13056 B
struct SmemXC   { float Hs[32][33]; float Cs[32][17]; float Ws[32][9]; };

#define SMEM_BYTES 17408

// ---------------- part: 1 + l2norm of one row ------------------------------
__device__ void part_norm(char* smem, int r,
                          const float* __restrict__ ye,
                          const float* __restrict__ ce) {
    SmemNorm& s = *reinterpret_cast<SmemNorm*>(smem);
    const float* src;
    float* dst;
    if (r < C) { src = ye + (size_t)r * H;        dst = g_y1 + (size_t)r * H; }
    else       { src = ce + (size_t)(r - C) * H;  dst = g_c1 + (size_t)(r - C) * H; }
    int t = threadIdx.x;
    float4 v = *reinterpret_cast<const float4*>(&src[t * 4]);
    s.red[t] = v.x * v.x + v.y * v.y + v.z * v.z + v.w * v.w;
    __syncthreads();
    for (int o = 128; o; o >>= 1) {
        if (t < o) s.red[t] += s.red[t + o];
        __syncthreads();
    }
    float n = fmaxf(sqrtf(s.red[0]), 1e-12f);
    dst[t * 4 + 0] = 1.0f + v.x / n;
    dst[t * 4 + 1] = 1.0f + v.y / n;
    dst[t * 4 + 2] = 1.0f + v.z / n;
    dst[t * 4 + 3] = 1.0f + v.w / n;
}

// ---------------- part: fc1 GEMM (f32x2, 64x64 tile) + bias + dropout ------
__device__ void part_fc1(char* smem, int which, int n0, int m0,
                         const float* __restrict__ x,
                         const float* __restrict__ W,
                         const float* __restrict__ B,
                         float* __restrict__ out) {
    SmemFc1& s = *reinterpret_cast<SmemFc1*>(smem);
    const int tid = threadIdx.x;
    const int tx = tid % 16, ty = tid / 16;   // tx: n group of 4, ty: m group of 4
    const int lr = tid / 4;                   // 0..63
    const int lc = (tid % 4) * 8;             // 0,8,16,24
    uint64_t acc[4][2] = {};
    for (int k0 = 0; k0 < D; k0 += 32) {
        {
            const float* xr = &x[(size_t)(m0 + lr) * D + k0 + lc];
            float4 a0 = *reinterpret_cast<const float4*>(xr);
            float4 a1 = *reinterpret_cast<const float4*>(xr + 4);
            const float* wr = &W[(size_t)(n0 + lr) * D + k0 + lc];
            float4 b0 = *reinterpret_cast<const float4*>(wr);
            float4 b1 = *reinterpret_cast<const float4*>(wr + 4);
            s.As[lc + 0][lr] = a0.x; s.As[lc + 1][lr] = a0.y;
            s.As[lc + 2][lr] = a0.z; s.As[lc + 3][lr] = a0.w;
            s.As[lc + 4][lr] = a1.x; s.As[lc + 5][lr] = a1.y;
            s.As[lc + 6][lr] = a1.z; s.As[lc + 7][lr] = a1.w;
            s.Bs[lc + 0][lr] = b0.x; s.Bs[lc + 1][lr] = b0.y;
            s.Bs[lc + 2][lr] = b0.z; s.Bs[lc + 3][lr] = b0.w;
            s.Bs[lc + 4][lr] = b1.x; s.Bs[lc + 5][lr] = b1.y;
            s.Bs[lc + 6][lr] = b1.z; s.Bs[lc + 7][lr] = b1.w;
        }
        __syncthreads();
#pragma unroll
        for (int kk = 0; kk < 32; kk++) {
            float4 a = *reinterpret_cast<const float4*>(&s.As[kk][ty * 4]);
            float4 b = *reinterpret_cast<const float4*>(&s.Bs[kk][tx * 4]);
            uint64_t b01 = pack2(b.x, b.y);
            uint64_t b23 = pack2(b.z, b.w);
            uint64_t ap;
            ap = pack2(a.x, a.x); fma2(acc[0][0], ap, b01); fma2(acc[0][1], ap, b23);
            ap = pack2(a.y, a.y); fma2(acc[1][0], ap, b01); fma2(acc[1][1], ap, b23);
            ap = pack2(a.z, a.z); fma2(acc[2][0], ap, b01); fma2(acc[2][1], ap, b23);
            ap = pack2(a.w, a.w); fma2(acc[3][0], ap, b01); fma2(acc[3][1], ap, b23);
        }
        __syncthreads();
    }
    uint32_t ka, kb;
    tf2x32(0u, 42u, 0u, (uint32_t)which, ka, kb);
#pragma unroll
    for (int i = 0; i < 4; i++) {
        int b = m0 + ty * 4 + i;
#pragma unroll
        for (int jp = 0; jp < 2; jp++) {
            float2 v = unpack2(acc[i][jp]);
            int col = n0 + tx * 4 + jp * 2;
            float h0 = v.x + B[col];
            float h1 = v.y + B[col + 1];
            uint32_t i0 = (uint32_t)(b * H + col);
            out[(size_t)b * H + col]     = drop_keep(ka, kb, i0)      ? h0 / 0.8f : 0.0f;
            out[(size_t)b * H + col + 1] = drop_keep(ka, kb, i0 + 1u) ? h1 / 0.8f : 0.0f;
        }
    }
}

// ---------------- part: stream concept_proj_w once (register-resident e) ----
// warp: 4 sequential rows, per-thread partials across rows, ONE batched
// butterfly reduction per 4 rows (keeps LDG stream un-stalled by shuffles).
__device__ void part_pnd(int n, int jg,
                         const float* __restrict__ ce,
                         const float* __restrict__ W) {
    const int tid = threadIdx.x;
    const int w = tid >> 5, lane = tid & 31;
    const int jbase = jg * 32 + w * 4;
    const size_t rs = (size_t)NC * H;
    float4 ep[8], en[8];
    {
        const float* epg = ce + (size_t)n * H + lane * 4;
        const float* eng = ce + (size_t)(NC + n) * H + lane * 4;
#pragma unroll
        for (int c = 0; c < 8; c++) {
            ep[c] = *reinterpret_cast<const float4*>(&epg[c * 128]);
            en[c] = *reinterpret_cast<const float4*>(&eng[c * 128]);
        }
    }
    const float* Wr = W + (size_t)jbase * rs + (size_t)n * H + lane * 4;
    float ap[4], an[4];
#pragma unroll
    for (int r = 0; r < 4; r++) { ap[r] = 0.f; an[r] = 0.f; }
#pragma unroll 1
    for (int r = 0; r < 4; r++) {
        const float* Wp = Wr + (size_t)r * rs;
        float4 wv[8];
#pragma unroll
        for (int c = 0; c < 8; c++)
            wv[c] = *reinterpret_cast<const float4*>(&Wp[c * 128]);
        float a = 0.f, b = 0.f;
#pragma unroll
        for (int c = 0; c < 8; c++) {
            a += wv[c].x * ep[c].x + wv[c].y * ep[c].y + wv[c].z * ep[c].z + wv[c].w * ep[c].w;
            b += wv[c].x * en[c].x + wv[c].y * en[c].y + wv[c].z * en[c].z + wv[c].w * en[c].w;
        }
        ap[r] = a; an[r] = b;
    }
    // batched butterfly: 8 independent chains, pipelined
#pragma unroll
    for (int off = 16; off; off >>= 1) {
#pragma unroll
        for (int r = 0; r < 4; r++) {
            ap[r] += __shfl_xor_sync(0xFFFFFFFFu, ap[r], off);
            an[r] += __shfl_xor_sync(0xFFFFFFFFu, an[r], off);
        }
    }
    if (lane == 0) {
#pragma unroll
        for (int r = 0; r < 4; r++) {
            g_pn[n * H + jbase + r] = an[r];
            g_pd[n * H + jbase + r] = ap[r] - an[r];
        }
    }
}

// ---------------- part: c_proj = (bias + sum_n pn) + gt @ pd ----------------
__device__ void part_cproj(char* smem, int j0, int m0,
                           const int* __restrict__ cgt,
                           const float* __restrict__ bias) {
    SmemCp& s = *reinterpret_cast<SmemCp*>(smem);
    const int tid = threadIdx.x;
    {
        int col = j0 + (tid & 63);
        if (tid < 64) s.base[tid] = bias[col];
        __syncthreads();
        int nb = (tid >> 6) * 28;
        float part = 0.f;
#pragma unroll 4
        for (int n = nb; n < nb + 28; n++) part += g_pn[n * H + col];
        atomicAdd(&s.base[tid & 63], part);
    }
    const int tx = tid % 16, ty = tid / 16;
    float acc[4][4] = {};
    for (int k0 = 0; k0 < NC; k0 += 16) {
        __syncthreads();
        {
            int r = tid / 4;
            int c = (tid % 4) * 4;
            int b = m0 + r;
#pragma unroll
            for (int q = 0; q < 4; q++)
                s.As[c + q][r] = (cgt[(size_t)b * NC + k0 + c + q] == 1) ? 1.0f : 0.0f;
        }
        {
            int kk = tid / 16;
            int j4 = (tid % 16) * 4;
            float4 v = *reinterpret_cast<const float4*>(&g_pd[(size_t)(k0 + kk) * H + j0 + j4]);
            *reinterpret_cast<float4*>(&s.Bs[kk][j4]) = v;
        }
        __syncthreads();
#pragma unroll
        for (int kk = 0; kk < 16; kk++) {
            float4 a = *reinterpret_cast<const float4*>(&s.As[kk][ty * 4]);
            float4 b = *reinterpret_cast<const float4*>(&s.Bs[kk][tx * 4]);
            float av[4] = {a.x, a.y, a.z, a.w};
            float bv[4] = {b.x, b.y, b.z, b.w};
#pragma unroll
            for (int i = 0; i < 4; i++)
#pragma unroll
                for (int j = 0; j < 4; j++)
                    acc[i][j] = fmaf(av[i], bv[j], acc[i][j]);
        }
    }
#pragma unroll
    for (int i = 0; i < 4; i++) {
        int b = m0 + ty * 4 + i;
#pragma unroll
        for (int j = 0; j < 4; j++) {
            int col = j0 + tx * 4 + j;
            g_cproj[(size_t)b * H + col] = acc[i][j] + s.base[tx * 4 + j];
        }
    }
}

// ---------------- part: xy / cy energy (32 c x 16 b tile, 64-k chunks) ------
__device__ void part_xycy(char* smem, int c0, int b0,
                          const float* __restrict__ A,
                          const float* __restrict__ clsw,
                          float bias,
                          float* __restrict__ out) {
    SmemXY& s = *reinterpret_cast<SmemXY*>(smem);
    const int tid = threadIdx.x;
    const int tx = tid % 16;   // c pair
    const int ty = tid / 16;   // b (0..15)
    float acc0 = 0.f, acc1 = 0.f;
    for (int k0 = 0; k0 < H; k0 += 64) {
        {
            int row = tid / 16, ko = (tid % 16) * 4;
            float4 v = *reinterpret_cast<const float4*>(&A[(size_t)(b0 + row) * H + k0 + ko]);
            s.Hs[ko + 0][row] = v.x; s.Hs[ko + 1][row] = v.y;
            s.Hs[ko + 2][row] = v.z; s.Hs[ko + 3][row] = v.w;
        }
        {
            int lr = tid / 8, lc = (tid % 8) * 4;
            int cr = c0 + lr; if (cr > C - 1) cr = C - 1;
            const float* yr = &g_y1[(size_t)cr * H + k0];
            float4 u = *reinterpret_cast<const float4*>(&yr[lc]);
            s.Ys[lc + 0][lr] = u.x; s.Ys[lc + 1][lr] = u.y;
            s.Ys[lc + 2][lr] = u.z; s.Ys[lc + 3][lr] = u.w;
            float4 u2 = *reinterpret_cast<const float4*>(&yr[32 + lc]);
            s.Ys[32 + lc + 0][lr] = u2.x; s.Ys[32 + lc + 1][lr] = u2.y;
            s.Ys[32 + lc + 2][lr] = u2.z; s.Ys[32 + lc + 3][lr] = u2.w;
        }
        if (tid < 64) s.ws[tid] = clsw[k0 + tid];
        __syncthreads();
#pragma unroll
        for (int kk = 0; kk < 64; kk++) {
            float h = s.Hs[kk][ty];
            float y0 = s.Ys[kk][tx * 2 + 0];
            float y1 = s.Ys[kk][tx * 2 + 1];
            float w = s.ws[kk];
            acc0 = fmaf(fmaxf(h * y0, 0.f), w, acc0);
            acc1 = fmaf(fmaxf(h * y1, 0.f), w, acc1);
        }
        __syncthreads();
    }
    int b = b0 + ty;
    int c = c0 + tx * 2;
    if (c < C)     out[(size_t)b * C + c]     = acc0 + bias;
    if (c + 1 < C) out[(size_t)b * C + c + 1] = acc1 + bias;
}

// ---------------- part: xc energy -------------------------------------------
__device__ void part_xc(char* smem, int n0, int b0,
                        const float* __restrict__ xcw,
                        const float* __restrict__ xcb,
                        float* __restrict__ out) {
    SmemXC& s = *reinterpret_cast<SmemXC*>(smem);
    const int tid = threadIdx.x;
    const int tx = tid % 8;
    const int ty = tid / 8;
    const int lr = tid / 8;
    const int lc = (tid % 8) * 4;
    float acc0 = 0.f, acc1 = 0.f;
    for (int k0 = 0; k0 < H; k0 += 32) {
        {
            float4 v = *reinterpret_cast<const float4*>(&g_hxc[(size_t)(b0 + lr) * H + k0 + lc]);
            s.Hs[lc + 0][lr] = v.x; s.Hs[lc + 1][lr] = v.y;
            s.Hs[lc + 2][lr] = v.z; s.Hs[lc + 3][lr] = v.w;
        }
        {
            int loc = tid / 16;
            int kk = (tid % 16) * 2;
            int nl = loc >> 1, sx = loc & 1;
            int row = sx * NC + (n0 + nl);
            float2 v = *reinterpret_cast<const float2*>(&g_c1[(size_t)row * H + k0 + kk]);
            s.Cs[kk + 0][nl * 2 + sx] = v.x;
            s.Cs[kk + 1][nl * 2 + sx] = v.y;
        }
        {
            int nl = tid / 32;
            int kk = tid % 32;
            s.Ws[kk][nl] = xcw[(size_t)(n0 + nl) * H + k0 + kk];
        }
        __syncthreads();
#pragma unroll
        for (int kk = 0; kk < 32; kk++) {
            float h = s.Hs[kk][ty];
            float w = s.Ws[kk][tx];
            float cp = s.Cs[kk][tx * 2 + 0];
            float cn = s.Cs[kk][tx * 2 + 1];
            acc0 = fmaf(fmaxf(h * cp, 0.f), w, acc0);
            acc1 = fmaf(fmaxf(h * cn, 0.f), w, acc1);
        }
        __syncthreads();
    }
    int b = b0 + ty, n = n0 + tx;
    float bb = xcb[n];
    size_t base = (size_t)(2 * BS * C) + (size_t)b * (NC * 2) + n * 2;
    out[base + 0] = acc0 + bb;
    out[base + 1] = acc1 + bb;
}

// ================= launch 1: fc1 + norm + pnd (overlapped) ==================
#define L1_FC1   128                          // 2 x (4 m-tiles x 16 n-tiles)
#define L1_NORM  (C + 2 * NC)                 // 424
#define L1_PND   (NC * 32)                    // 3584
#define L1_GRID  (L1_FC1 + L1_NORM + L1_PND)

__global__ __launch_bounds__(256, 2) void k_main(const float* __restrict__ x,
                                                 const float* __restrict__ ye,
                                                 const float* __restrict__ ce,
                                                 const float* __restrict__ w0,
                                                 const float* __restrict__ b0,
                                                 const float* __restrict__ w1,
                                                 const float* __restrict__ b1,
                                                 const float* __restrict__ cpw) {
    __shared__ __align__(16) char smem[SMEM_BYTES];
    int bid = blockIdx.x;
    if (bid < L1_FC1) {
        int which = bid >> 6;
        int rem = bid & 63;
        part_fc1(smem, which, (rem % 16) * 64, (rem / 16) * 64, x,
                 which ? w1 : w0, which ? b1 : b0, which ? g_hxc : g_hxy);
    } else if (bid < L1_FC1 + L1_NORM) {
        part_norm(smem, bid - L1_FC1, ye, ce);
    } else {
        int p = bid - (L1_FC1 + L1_NORM);
        part_pnd(p % NC, p / NC, ce, cpw);
    }
}

// ================= launch 2: cproj + xy-energy + xc-energy ==================
#define L2_CP   (16 * 4)              // 64
#define L2_XY   (7 * 16)              // 112
#define L2_XC   (14 * 8)              // 112
#define L2_GRID (L2_CP + L2_XY + L2_XC)

__global__ __launch_bounds__(256) void k_mid(const int* __restrict__ cgt,
                                             const float* __restrict__ cpb,
                                             const float* __restrict__ clsxy_w,
                                             const float* __restrict__ clsxy_b,
                                             const float* __restrict__ xcw,
                                             const float* __restrict__ xcb,
                                             float* __restrict__ out) {
    __shared__ __align__(16) char smem[SMEM_BYTES];
    int bid = blockIdx.x;
    if (bid < L2_CP) {
        part_cproj(smem, (bid % 16) * 64, (bid / 16) * 64, cgt, cpb);
    } else if (bid < L2_CP + L2_XY) {
        int p = bid - L2_CP;
        part_xycy(smem, (p % 7) * 32, (p / 7) * 16, g_hxy, clsxy_w, clsxy_b[0], out);
    } else {
        int p = bid - (L2_CP + L2_XY);
        part_xc(smem, (p % 14) * 8, (p / 14) * 32, xcw, xcb, out);
    }
}

// ================= launch 3: cy-energy ======================================
__global__ __launch_bounds__(256) void k_cy(const float* __restrict__ clscy_w,
                                            const float* __restrict__ clscy_b,
                                            float* __restrict__ out) {
    __shared__ __align__(16) char smem[SMEM_BYTES];
    int bid = blockIdx.x;
    part_xycy(smem, (bid % 7) * 32, (bid / 7) * 16, g_cproj, clscy_w, clscy_b[0],
              out + (size_t)BS * C);
}

// ---------------- launch ----------------------------------------------------
extern "C" void kernel_launch(void* const* d_in, const int* in_sizes, int n_in,
                              void* d_out, int out_size) {
    (void)in_sizes; (void)n_in; (void)out_size;
    const float* x       = (const float*)d_in[0];
    const int*   c_gt    = (const int*)d_in[1];
    const float* y_emb   = (const float*)d_in[2];
    const float* c_emb   = (const float*)d_in[3];
    const float* xy_w    = (const float*)d_in[4];
    const float* xy_b    = (const float*)d_in[5];
    const float* xc_w1   = (const float*)d_in[6];
    const float* xc_b1   = (const float*)d_in[7];
    const float* clsxy_w = (const float*)d_in[8];
    const float* clsxy_b = (const float*)d_in[9];
    const float* clscy_w = (const float*)d_in[10];
    const float* clscy_b = (const float*)d_in[11];
    const float* xcw     = (const float*)d_in[12];
    const float* xcb     = (const float*)d_in[13];
    const float* cpw     = (const float*)d_in[14];
    const float* cpb     = (const float*)d_in[15];
    float* out = (float*)d_out;

    k_main<<<L1_GRID, 256>>>(x, y_emb, c_emb, xy_w, xy_b, xc_w1, xc_b1, cpw);
    k_mid<<<L2_GRID, 256>>>(c_gt, cpb, clsxy_w, clsxy_b, xcw, xcb, out);
    k_cy<<<7 * 16, 256>>>(clscy_w, clscy_b, out);
}